// round 1
// baseline (speedup 1.0000x reference)
#include <cuda_runtime.h>
#include <math.h>
#include <stdint.h>

// Problem constants
#define LAYERS 2
#define BATCH  4
#define SEQ    1024
#define HID    2048
#define NHEAD  16
#define HDIM   128          // HID / NHEAD
#define H3     (3*HID)      // 6144
#define H4     (4*HID)      // 8192
#define ROWS   (BATCH*SEQ)  // 4096
#define NHEADS_TOT (BATCH*NHEAD) // 64
#define EPSV   1e-5f

// ---------------------------------------------------------------------------
// Scratch buffers (device globals; allocation is forbidden in kernel_launch)
// ---------------------------------------------------------------------------
__device__ float g_h   [(size_t)ROWS*HID];       // residual stream h
__device__ float g_x   [(size_t)ROWS*HID];       // LN output / temp
__device__ float g_qkv [(size_t)ROWS*H3];        // qkv projection
__device__ float g_scr [(size_t)NHEADS_TOT*SEQ*SEQ]; // attention scores/probs
__device__ float g_ctx [(size_t)ROWS*HID];       // attention context
__device__ float g_att [(size_t)ROWS*HID];       // dense proj output
__device__ float g_h2  [(size_t)ROWS*HID];       // h + LN(attn)
__device__ float g_m1  [(size_t)ROWS*H4];        // mlp intermediate
__device__ float g_m2  [(size_t)ROWS*HID];       // mlp output

// ---------------------------------------------------------------------------
// Block reduction helpers (256 threads)
// ---------------------------------------------------------------------------
__device__ __forceinline__ float blockReduceSum256(float v) {
    __shared__ float sm[8];
    int lane = threadIdx.x & 31, w = threadIdx.x >> 5;
    #pragma unroll
    for (int o = 16; o > 0; o >>= 1) v += __shfl_xor_sync(0xffffffffu, v, o);
    if (lane == 0) sm[w] = v;
    __syncthreads();
    float r = sm[0];
    #pragma unroll
    for (int i = 1; i < 8; i++) r += sm[i];
    __syncthreads();
    return r;
}

__device__ __forceinline__ float blockReduceMax256(float v) {
    __shared__ float sm[8];
    int lane = threadIdx.x & 31, w = threadIdx.x >> 5;
    #pragma unroll
    for (int o = 16; o > 0; o >>= 1) v = fmaxf(v, __shfl_xor_sync(0xffffffffu, v, o));
    if (lane == 0) sm[w] = v;
    __syncthreads();
    float r = sm[0];
    #pragma unroll
    for (int i = 1; i < 8; i++) r = fmaxf(r, sm[i]);
    __syncthreads();
    return r;
}

// ---------------------------------------------------------------------------
// LayerNorm: out[row] = (res ? res[row] : 0) + LN(x[row]) * g + b
// one block (256 thr) per row of H=2048
// ---------------------------------------------------------------------------
__global__ __launch_bounds__(256) void ln_kernel(
    const float* __restrict__ x, const float* __restrict__ gamma,
    const float* __restrict__ beta, const float* __restrict__ res,
    float* __restrict__ out)
{
    const int row = blockIdx.x;
    const int tid = threadIdx.x;
    const float* xr = x + (size_t)row * HID;

    float v[8];
    float s = 0.f;
    #pragma unroll
    for (int i = 0; i < 8; i++) { v[i] = xr[i*256 + tid]; s += v[i]; }
    s = blockReduceSum256(s);
    const float mean = s * (1.0f / HID);

    float q = 0.f;
    #pragma unroll
    for (int i = 0; i < 8; i++) { float d = v[i] - mean; q += d * d; }
    q = blockReduceSum256(q);
    const float rstd = rsqrtf(q * (1.0f / HID) + EPSV);

    float* orow = out + (size_t)row * HID;
    const float* rrow = res ? res + (size_t)row * HID : nullptr;
    #pragma unroll
    for (int i = 0; i < 8; i++) {
        int c = i*256 + tid;
        float o = (v[i] - mean) * rstd * gamma[c] + beta[c];
        if (rrow) o += rrow[c];
        orow[c] = o;
    }
}

// ---------------------------------------------------------------------------
// GELU
// ---------------------------------------------------------------------------
__device__ __forceinline__ float gelu_f(float x) {
    float inner = 0.7978845608028654f * x * (1.0f + 0.044715f * x * x);
    return 0.5f * x * (1.0f + tanhf(inner));
}

// ---------------------------------------------------------------------------
// SGEMM: C[M,N] = A[M,K] @ W[N,K]^T + bias[N]   (both operands K-major)
// 128x128 tile, BK=16, 256 threads, 8x8 per thread. M,N,K multiples of 128/16.
// ---------------------------------------------------------------------------
template<int GELU>
__global__ __launch_bounds__(256) void sgemm_nt(
    const float* __restrict__ A, const float* __restrict__ W,
    const float* __restrict__ bias, float* __restrict__ C,
    int M, int N, int K)
{
    constexpr int BM = 128, BN = 128, BK = 16;
    __shared__ float As[BK][BM + 4];
    __shared__ float Bs[BK][BN + 4];

    const int bm = blockIdx.y * BM;
    const int bn = blockIdx.x * BN;
    const int tid = threadIdx.x;
    const int tx = tid & 15;          // 0..15  (N dir)
    const int ty = tid >> 4;          // 0..15  (M dir)

    const float* Ab = A + (size_t)bm * K;
    const float* Wb = W + (size_t)bn * K;

    float acc[8][8] = {};

    for (int k0 = 0; k0 < K; k0 += BK) {
        #pragma unroll
        for (int i = 0; i < 2; i++) {
            int f   = tid + i * 256;      // 0..511
            int row = f >> 2;             // 0..127
            int kc  = (f & 3) * 4;        // 0,4,8,12
            float4 a = *(const float4*)(Ab + (size_t)row * K + k0 + kc);
            As[kc+0][row] = a.x; As[kc+1][row] = a.y;
            As[kc+2][row] = a.z; As[kc+3][row] = a.w;
            float4 w = *(const float4*)(Wb + (size_t)row * K + k0 + kc);
            Bs[kc+0][row] = w.x; Bs[kc+1][row] = w.y;
            Bs[kc+2][row] = w.z; Bs[kc+3][row] = w.w;
        }
        __syncthreads();

        #pragma unroll
        for (int kk = 0; kk < BK; kk++) {
            float a[8], b[8];
            #pragma unroll
            for (int j = 0; j < 8; j++) a[j] = As[kk][ty*8 + j];
            #pragma unroll
            for (int j = 0; j < 8; j++) b[j] = Bs[kk][tx*8 + j];
            #pragma unroll
            for (int i = 0; i < 8; i++)
                #pragma unroll
                for (int j = 0; j < 8; j++)
                    acc[i][j] += a[i] * b[j];
        }
        __syncthreads();
    }

    // epilogue: bias (+gelu), vectorized stores
    const int nbase = bn + tx*8;
    float bvals[8];
    #pragma unroll
    for (int j = 0; j < 8; j++) bvals[j] = bias[nbase + j];

    #pragma unroll
    for (int i = 0; i < 8; i++) {
        int m = bm + ty*8 + i;
        float o[8];
        #pragma unroll
        for (int j = 0; j < 8; j++) {
            float vv = acc[i][j] + bvals[j];
            o[j] = GELU ? gelu_f(vv) : vv;
        }
        float4* dst = (float4*)(C + (size_t)m * N + nbase);
        dst[0] = make_float4(o[0], o[1], o[2], o[3]);
        dst[1] = make_float4(o[4], o[5], o[6], o[7]);
    }
}

// ---------------------------------------------------------------------------
// Attention scores: scr[hd, s, t] = (q_s . k_t) / sqrt(HDIM), causal tiles only
// 64x64 tile, K=128 in 4 chunks of 32, 256 threads, 4x4 per thread
// ---------------------------------------------------------------------------
__global__ __launch_bounds__(256) void attn_scores(
    const float* __restrict__ qkv, float* __restrict__ scr)
{
    const int tt = blockIdx.x;   // t tile
    const int st = blockIdx.y;   // s tile
    if (tt > st) return;         // causal skip
    const int hd = blockIdx.z;   // 0..63
    const int b  = hd >> 4, n = hd & 15;

    const float* Q  = qkv + (size_t)b * SEQ * H3 + n * HDIM;
    const float* Kp = Q + HID;

    __shared__ float Qs[32][68];
    __shared__ float Ks[32][68];

    const int tid = threadIdx.x;
    const int tx = tid & 15, ty = tid >> 4;
    const int s0 = st * 64, t0 = tt * 64;

    float acc[4][4] = {};

    for (int k0 = 0; k0 < HDIM; k0 += 32) {
        #pragma unroll
        for (int i = 0; i < 2; i++) {
            int f   = tid + i * 256;  // 0..511
            int row = f >> 3;         // 0..63
            int kc  = (f & 7) * 4;    // 0..28
            float4 q = *(const float4*)(Q  + (size_t)(s0+row) * H3 + k0 + kc);
            Qs[kc+0][row] = q.x; Qs[kc+1][row] = q.y;
            Qs[kc+2][row] = q.z; Qs[kc+3][row] = q.w;
            float4 k = *(const float4*)(Kp + (size_t)(t0+row) * H3 + k0 + kc);
            Ks[kc+0][row] = k.x; Ks[kc+1][row] = k.y;
            Ks[kc+2][row] = k.z; Ks[kc+3][row] = k.w;
        }
        __syncthreads();
        #pragma unroll
        for (int kk = 0; kk < 32; kk++) {
            float4 av = *(const float4*)&Qs[kk][ty*4];
            float4 bv = *(const float4*)&Ks[kk][tx*4];
            float a[4] = {av.x, av.y, av.z, av.w};
            float bb[4] = {bv.x, bv.y, bv.z, bv.w};
            #pragma unroll
            for (int i = 0; i < 4; i++)
                #pragma unroll
                for (int j = 0; j < 4; j++)
                    acc[i][j] += a[i] * bb[j];
        }
        __syncthreads();
    }

    const float scale = 0.08838834764831845f; // 1/sqrt(128)
    #pragma unroll
    for (int i = 0; i < 4; i++) {
        int s = s0 + ty*4 + i;
        float4* dst = (float4*)(scr + ((size_t)hd * SEQ + s) * SEQ + t0 + tx*4);
        dst[0] = make_float4(acc[i][0]*scale, acc[i][1]*scale,
                             acc[i][2]*scale, acc[i][3]*scale);
    }
}

// ---------------------------------------------------------------------------
// Causal row softmax in place; zero the intra-tile upper triangle so the PV
// kernel can iterate whole 64-wide t-tiles.
// ---------------------------------------------------------------------------
__global__ __launch_bounds__(256) void softmax_causal(float* __restrict__ scr)
{
    const int s  = blockIdx.x;
    const int hd = blockIdx.y;
    float* row = scr + ((size_t)hd * SEQ + s) * SEQ;
    const int len = s + 1;
    const int tid = threadIdx.x;

    float e[4];
    float mx = -1e30f;
    #pragma unroll
    for (int i = 0; i < 4; i++) {
        int t = tid + i*256;
        e[i] = (t < len) ? row[t] : -1e30f;
        mx = fmaxf(mx, e[i]);
    }
    mx = blockReduceMax256(mx);

    float sum = 0.f;
    #pragma unroll
    for (int i = 0; i < 4; i++) {
        int t = tid + i*256;
        if (t < len) { e[i] = expf(e[i] - mx); sum += e[i]; }
        else e[i] = 0.f;
    }
    sum = blockReduceSum256(sum);
    const float inv = 1.0f / sum;

    const int tile_end = ((s >> 6) + 1) << 6;
    #pragma unroll
    for (int i = 0; i < 4; i++) {
        int t = tid + i*256;
        if (t < len)            row[t] = e[i] * inv;
        else if (t < tile_end)  row[t] = 0.f;
    }
}

// ---------------------------------------------------------------------------
// PV: ctx[b, s, n*128 + c] = sum_t P[hd,s,t] * V[t,c]
// 64 s-rows x 128 cols per block, t in chunks of 32. 256 threads: 8x4/thread.
// ---------------------------------------------------------------------------
__global__ __launch_bounds__(256) void attn_pv(
    const float* __restrict__ scr, const float* __restrict__ qkv,
    float* __restrict__ ctx)
{
    const int st = blockIdx.x;   // 0..15
    const int hd = blockIdx.y;   // 0..63
    const int b  = hd >> 4, n = hd & 15;

    const float* V = qkv + (size_t)b * SEQ * H3 + 2*HID + n * HDIM;
    const float* P = scr + ((size_t)hd * SEQ + st*64) * SEQ;

    __shared__ float Ps[64][36];
    __shared__ float Vs[32][128];

    const int tid = threadIdx.x;
    const int tr = tid >> 5;   // 0..7  (row group)
    const int tc = tid & 31;   // 0..31 (col group)

    float acc[8][4] = {};
    const int nk = (st + 1) * 64;

    for (int t0 = 0; t0 < nk; t0 += 32) {
        #pragma unroll
        for (int i = 0; i < 2; i++) {
            int f   = tid + i*256;    // 0..511
            int row = f >> 3;         // 0..63
            int kc  = (f & 7) * 4;    // 0..28
            float4 p = *(const float4*)(P + (size_t)row * SEQ + t0 + kc);
            *(float4*)&Ps[row][kc] = p;
        }
        #pragma unroll
        for (int i = 0; i < 4; i++) {
            int f   = tid + i*256;    // 0..1023
            int row = f >> 5;         // 0..31
            int c   = (f & 31) * 4;   // 0..124
            float4 v = *(const float4*)(V + (size_t)(t0+row) * H3 + c);
            *(float4*)&Vs[row][c] = v;
        }
        __syncthreads();

        #pragma unroll
        for (int kk = 0; kk < 32; kk++) {
            float4 vv = *(const float4*)&Vs[kk][tc*4];
            #pragma unroll
            for (int j = 0; j < 8; j++) {
                float p = Ps[tr*8 + j][kk];
                acc[j][0] += p * vv.x;
                acc[j][1] += p * vv.y;
                acc[j][2] += p * vv.z;
                acc[j][3] += p * vv.w;
            }
        }
        __syncthreads();
    }

    #pragma unroll
    for (int j = 0; j < 8; j++) {
        int s = st*64 + tr*8 + j;
        float4* dst = (float4*)(ctx + ((size_t)b*SEQ + s) * HID + n*HDIM + tc*4);
        dst[0] = make_float4(acc[j][0], acc[j][1], acc[j][2], acc[j][3]);
    }
}

// ---------------------------------------------------------------------------
// Host side
// ---------------------------------------------------------------------------
static float* symaddr(const void* sym) {
    void* p = nullptr;
    cudaGetSymbolAddress(&p, sym);
    return (float*)p;
}

extern "C" void kernel_launch(void* const* d_in, const int* in_sizes, int n_in,
                              void* d_out, int out_size)
{
    const float* hidden  = (const float*)d_in[0];
    // d_in[1] = ltor_mask (full causal; handled analytically)
    const float* qkv_w   = (const float*)d_in[2];
    const float* qkv_b   = (const float*)d_in[3];
    const float* dense_w = (const float*)d_in[4];
    const float* dense_b = (const float*)d_in[5];
    const float* mlp_w1  = (const float*)d_in[6];
    const float* mlp_b1  = (const float*)d_in[7];
    const float* mlp_w2  = (const float*)d_in[8];
    const float* mlp_b2  = (const float*)d_in[9];
    const float* ln_in_g   = (const float*)d_in[10];
    const float* ln_in_b   = (const float*)d_in[11];
    const float* ln_post_g = (const float*)d_in[12];
    const float* ln_post_b = (const float*)d_in[13];
    const float* ln_s1_g   = (const float*)d_in[14];
    const float* ln_s1_b   = (const float*)d_in[15];
    const float* ln_s2_g   = (const float*)d_in[16];
    const float* ln_s2_b   = (const float*)d_in[17];

    float* h   = symaddr(g_h);
    float* x   = symaddr(g_x);
    float* qkv = symaddr(g_qkv);
    float* scr = symaddr(g_scr);
    float* ctx = symaddr(g_ctx);
    float* att = symaddr(g_att);
    float* h2  = symaddr(g_h2);
    float* m1  = symaddr(g_m1);
    float* m2  = symaddr(g_m2);
    float* out = (float*)d_out;

    const size_t hbytes = (size_t)ROWS * HID * sizeof(float);
    cudaMemcpyAsync(h, hidden, hbytes, cudaMemcpyDeviceToDevice, 0);

    for (int l = 0; l < LAYERS; l++) {
        const float* l_qkv_w   = qkv_w   + (size_t)l * H3 * HID;
        const float* l_qkv_b   = qkv_b   + (size_t)l * H3;
        const float* l_dense_w = dense_w + (size_t)l * HID * HID;
        const float* l_dense_b = dense_b + (size_t)l * HID;
        const float* l_w1      = mlp_w1  + (size_t)l * H4 * HID;
        const float* l_b1      = mlp_b1  + (size_t)l * H4;
        const float* l_w2      = mlp_w2  + (size_t)l * HID * H4;
        const float* l_b2      = mlp_b2  + (size_t)l * HID;

        // x = LN_in(h)
        ln_kernel<<<ROWS, 256>>>(h, ln_in_g + l*HID, ln_in_b + l*HID, nullptr, x);

        // qkv = x @ qkv_w^T + qkv_b
        sgemm_nt<0><<<dim3(H3/128, ROWS/128), 256>>>(x, l_qkv_w, l_qkv_b, qkv,
                                                     ROWS, H3, HID);
        // scores (causal tiles)
        attn_scores<<<dim3(16, 16, NHEADS_TOT), 256>>>(qkv, scr);
        // softmax
        softmax_causal<<<dim3(SEQ, NHEADS_TOT), 256>>>(scr);
        // ctx = probs @ V
        attn_pv<<<dim3(16, NHEADS_TOT), 256>>>(scr, qkv, ctx);

        // attn_out = ctx @ dense_w^T + dense_b
        sgemm_nt<0><<<dim3(HID/128, ROWS/128), 256>>>(ctx, l_dense_w, l_dense_b,
                                                      att, ROWS, HID, HID);
        // h2 = h + LN_s1(attn_out)
        ln_kernel<<<ROWS, 256>>>(att, ln_s1_g + l*HID, ln_s1_b + l*HID, h, h2);

        // y = LN_post(h2)
        ln_kernel<<<ROWS, 256>>>(h2, ln_post_g + l*HID, ln_post_b + l*HID, nullptr, x);
        // m1 = gelu(y @ w1^T + b1)
        sgemm_nt<1><<<dim3(H4/128, ROWS/128), 256>>>(x, l_w1, l_b1, m1,
                                                     ROWS, H4, HID);
        // m2 = m1 @ w2^T + b2
        sgemm_nt<0><<<dim3(HID/128, ROWS/128), 256>>>(m1, l_w2, l_b2, m2,
                                                      ROWS, HID, H4);
        // h = h2 + LN_s2(m2)
        ln_kernel<<<ROWS, 256>>>(m2, ln_s2_g + l*HID, ln_s2_b + l*HID, h2, h);
    }

    cudaMemcpyAsync(out, h, hbytes, cudaMemcpyDeviceToDevice, 0);
}

// round 3
// speedup vs baseline: 3.7309x; 3.7309x over previous
#include <cuda_runtime.h>
#include <cuda_bf16.h>
#include <math.h>
#include <stdint.h>

// Problem constants
#define LAYERS 2
#define BATCH  4
#define SEQ    1024
#define HID    2048
#define NHEAD  16
#define HDIM   128
#define H3     (3*HID)
#define H4     (4*HID)
#define ROWS   (BATCH*SEQ)
#define NHEADS_TOT (BATCH*NHEAD)
#define EPSV   1e-5f

// ---------------------------------------------------------------------------
// Scratch (device globals)
// ---------------------------------------------------------------------------
__device__ float g_h   [(size_t)ROWS*HID];
__device__ float g_x   [(size_t)ROWS*HID];
__device__ float g_qkv [(size_t)ROWS*H3];
__device__ float g_scr [(size_t)NHEADS_TOT*SEQ*SEQ];
__device__ float g_ctx [(size_t)ROWS*HID];
__device__ float g_att [(size_t)ROWS*HID];
__device__ float g_h2  [(size_t)ROWS*HID];
__device__ float g_m1  [(size_t)ROWS*H4];
__device__ float g_m2  [(size_t)ROWS*HID];
// bf16 split buffers
__device__ __nv_bfloat16 g_a0[(size_t)ROWS*H4];
__device__ __nv_bfloat16 g_a1[(size_t)ROWS*H4];
__device__ __nv_bfloat16 g_w0[(size_t)H4*HID];
__device__ __nv_bfloat16 g_w1[(size_t)H4*HID];

// ---------------------------------------------------------------------------
// Small helpers
// ---------------------------------------------------------------------------
__device__ __forceinline__ uint32_t smem_u32(const void* p) {
    uint32_t a;
    asm("{ .reg .u64 t; cvta.to.shared.u64 t, %1; cvt.u32.u64 %0, t; }"
        : "=r"(a) : "l"(p));
    return a;
}
__device__ __forceinline__ void cp16(uint32_t dst, const void* src) {
    asm volatile("cp.async.cg.shared.global [%0], [%1], 16;"
                 :: "r"(dst), "l"(src) : "memory");
}
__device__ __forceinline__ void cp_commit() {
    asm volatile("cp.async.commit_group;" ::: "memory");
}
template<int N> __device__ __forceinline__ void cp_wait() {
    asm volatile("cp.async.wait_group %0;" :: "n"(N) : "memory");
}
__device__ __forceinline__ void mma16816(float* d, const uint32_t* a, const uint32_t* b) {
    asm volatile(
        "mma.sync.aligned.m16n8k16.row.col.f32.bf16.bf16.f32 "
        "{%0,%1,%2,%3}, {%4,%5,%6,%7}, {%8,%9}, {%0,%1,%2,%3};"
        : "+f"(d[0]), "+f"(d[1]), "+f"(d[2]), "+f"(d[3])
        : "r"(a[0]), "r"(a[1]), "r"(a[2]), "r"(a[3]), "r"(b[0]), "r"(b[1]));
}

// ---------------------------------------------------------------------------
// Reductions / LN / GELU
// ---------------------------------------------------------------------------
__device__ __forceinline__ float blockReduceSum256(float v) {
    __shared__ float sm[8];
    int lane = threadIdx.x & 31, w = threadIdx.x >> 5;
    #pragma unroll
    for (int o = 16; o > 0; o >>= 1) v += __shfl_xor_sync(0xffffffffu, v, o);
    if (lane == 0) sm[w] = v;
    __syncthreads();
    float r = sm[0];
    #pragma unroll
    for (int i = 1; i < 8; i++) r += sm[i];
    __syncthreads();
    return r;
}
__device__ __forceinline__ float blockReduceMax256(float v) {
    __shared__ float sm[8];
    int lane = threadIdx.x & 31, w = threadIdx.x >> 5;
    #pragma unroll
    for (int o = 16; o > 0; o >>= 1) v = fmaxf(v, __shfl_xor_sync(0xffffffffu, v, o));
    if (lane == 0) sm[w] = v;
    __syncthreads();
    float r = sm[0];
    #pragma unroll
    for (int i = 1; i < 8; i++) r = fmaxf(r, sm[i]);
    __syncthreads();
    return r;
}

__global__ __launch_bounds__(256) void ln_kernel(
    const float* __restrict__ x, const float* __restrict__ gamma,
    const float* __restrict__ beta, const float* __restrict__ res,
    float* __restrict__ out)
{
    const int row = blockIdx.x;
    const int tid = threadIdx.x;
    const float* xr = x + (size_t)row * HID;

    float v[8];
    float s = 0.f;
    #pragma unroll
    for (int i = 0; i < 8; i++) { v[i] = xr[i*256 + tid]; s += v[i]; }
    s = blockReduceSum256(s);
    const float mean = s * (1.0f / HID);

    float q = 0.f;
    #pragma unroll
    for (int i = 0; i < 8; i++) { float d = v[i] - mean; q += d * d; }
    q = blockReduceSum256(q);
    const float rstd = rsqrtf(q * (1.0f / HID) + EPSV);

    float* orow = out + (size_t)row * HID;
    const float* rrow = res ? res + (size_t)row * HID : nullptr;
    #pragma unroll
    for (int i = 0; i < 8; i++) {
        int c = i*256 + tid;
        float o = (v[i] - mean) * rstd * gamma[c] + beta[c];
        if (rrow) o += rrow[c];
        orow[c] = o;
    }
}

__device__ __forceinline__ float gelu_f(float x) {
    float inner = 0.7978845608028654f * x * (1.0f + 0.044715f * x * x);
    return 0.5f * x * (1.0f + tanhf(inner));
}

// ---------------------------------------------------------------------------
// fp32 -> bf16 hi/lo split
// ---------------------------------------------------------------------------
__global__ __launch_bounds__(256) void split_fp32_bf16(
    const float* __restrict__ src, __nv_bfloat16* __restrict__ hi,
    __nv_bfloat16* __restrict__ lo, int n4)
{
    int i = blockIdx.x * 256 + threadIdx.x;
    if (i >= n4) return;
    float4 v = reinterpret_cast<const float4*>(src)[i];
    __nv_bfloat16 h0 = __float2bfloat16(v.x);
    __nv_bfloat16 h1 = __float2bfloat16(v.y);
    __nv_bfloat16 h2 = __float2bfloat16(v.z);
    __nv_bfloat16 h3 = __float2bfloat16(v.w);
    __nv_bfloat16 l0 = __float2bfloat16(v.x - __bfloat162float(h0));
    __nv_bfloat16 l1 = __float2bfloat16(v.y - __bfloat162float(h1));
    __nv_bfloat16 l2 = __float2bfloat16(v.z - __bfloat162float(h2));
    __nv_bfloat16 l3 = __float2bfloat16(v.w - __bfloat162float(h3));
    __nv_bfloat162* hp = reinterpret_cast<__nv_bfloat162*>(hi);
    __nv_bfloat162* lp = reinterpret_cast<__nv_bfloat162*>(lo);
    hp[2*i + 0] = __halves2bfloat162(h0, h1);
    hp[2*i + 1] = __halves2bfloat162(h2, h3);
    lp[2*i + 0] = __halves2bfloat162(l0, l1);
    lp[2*i + 1] = __halves2bfloat162(l2, l3);
}

// ---------------------------------------------------------------------------
// bf16 split-3 GEMM via mma.sync (sm_80-compatible HMMA path):
//   C[M,N] = (A0+A1)[M,K] @ (B0+B1)[N,K]^T + bias, dropping A1*B1.
// Block tile 128x128, BK=32, 8 warps (4x2), warp tile 32x64.
// Smem rows padded to 80B (20 words): conflict-free for (g, c) fragment loads.
// cp.async double-buffered.
// ---------------------------------------------------------------------------
#define STRIDE_W 20                    // words per smem row (80B)
#define TILE_W   (128*STRIDE_W)        // 2560 words per tile
#define STAGE_W  (4*TILE_W)            // 10240 words per stage
#define GEMM_SMEM_DYN (2*STAGE_W*4)    // 81920 bytes

template<int GELU>
__global__ __launch_bounds__(256) void gemm_tc(
    const __nv_bfloat16* __restrict__ A0, const __nv_bfloat16* __restrict__ A1,
    const __nv_bfloat16* __restrict__ B0, const __nv_bfloat16* __restrict__ B1,
    const float* __restrict__ bias, float* __restrict__ C,
    int M, int N, int K)
{
    extern __shared__ uint32_t smw[];
    const uint32_t smbase = smem_u32(smw);

    const int tid  = threadIdx.x;
    const int wid  = tid >> 5, lane = tid & 31;
    const int bm   = blockIdx.y * 128;
    const int bn   = blockIdx.x * 128;
    const int wm   = wid & 3;          // 0..3 (M dir, 32 rows each)
    const int wn   = wid >> 2;         // 0..1 (N dir, 64 cols each)
    const int g    = lane >> 2;        // 0..7
    const int c    = lane & 3;         // 0..3

    const char* gA0 = (const char*)(A0 + (size_t)bm * K);
    const char* gA1 = (const char*)(A1 + (size_t)bm * K);
    const char* gB0 = (const char*)(B0 + (size_t)bn * K);
    const char* gB1 = (const char*)(B1 + (size_t)bn * K);
    const size_t rs = (size_t)K * 2;

    const int nIter = K >> 5;

    // stage loader: 4 tiles x 128 rows x 4 chunks of 16B = 2048 cp.async
    auto load_stage = [&](int it, int buf) {
        const uint32_t sb = smbase + (uint32_t)buf * (STAGE_W * 4);
        const size_t ko = (size_t)it * 64;  // bytes along K
        #pragma unroll
        for (int i = 0; i < 8; i++) {
            int idx = tid + i * 256;           // 0..2047
            int t  = idx >> 9;                 // tile id
            int r  = (idx >> 2) & 127;         // row
            int ch = idx & 3;                  // 16B chunk
            const char* base = (t == 0) ? gA0 : (t == 1) ? gA1 : (t == 2) ? gB0 : gB1;
            const char* src = base + (size_t)r * rs + ko + (size_t)ch * 16;
            uint32_t dst = sb + (uint32_t)(t * (TILE_W * 4) + r * 80 + ch * 16);
            cp16(dst, src);
        }
    };

    float acc[2][8][4];
    #pragma unroll
    for (int i = 0; i < 2; i++)
        #pragma unroll
        for (int j = 0; j < 8; j++)
            #pragma unroll
            for (int k = 0; k < 4; k++) acc[i][j][k] = 0.f;

    load_stage(0, 0);
    cp_commit();

    for (int it = 0; it < nIter; ++it) {
        const int buf = it & 1;
        if (it + 1 < nIter) {
            load_stage(it + 1, buf ^ 1);
            cp_commit();
            cp_wait<1>();
        } else {
            cp_wait<0>();
        }
        __syncthreads();

        const uint32_t* s    = smw + buf * STAGE_W;
        const uint32_t* sA0t = s;
        const uint32_t* sA1t = s + TILE_W;
        const uint32_t* sB0t = s + 2 * TILE_W;
        const uint32_t* sB1t = s + 3 * TILE_W;

        #pragma unroll
        for (int ks = 0; ks < 2; ++ks) {
            const int ko = ks * 8 + c;
            uint32_t a0f[2][4], a1f[2][4];
            #pragma unroll
            for (int fm = 0; fm < 2; ++fm) {
                int r = (wm * 32 + fm * 16 + g) * STRIDE_W + ko;
                a0f[fm][0] = sA0t[r];
                a0f[fm][1] = sA0t[r + 8 * STRIDE_W];
                a0f[fm][2] = sA0t[r + 4];
                a0f[fm][3] = sA0t[r + 8 * STRIDE_W + 4];
                a1f[fm][0] = sA1t[r];
                a1f[fm][1] = sA1t[r + 8 * STRIDE_W];
                a1f[fm][2] = sA1t[r + 4];
                a1f[fm][3] = sA1t[r + 8 * STRIDE_W + 4];
            }
            uint32_t b0f[8][2], b1f[8][2];
            #pragma unroll
            for (int fn = 0; fn < 8; ++fn) {
                int r = (wn * 64 + fn * 8 + g) * STRIDE_W + ko;
                b0f[fn][0] = sB0t[r];
                b0f[fn][1] = sB0t[r + 4];
                b1f[fn][0] = sB1t[r];
                b1f[fn][1] = sB1t[r + 4];
            }
            #pragma unroll
            for (int fm = 0; fm < 2; ++fm)
                #pragma unroll
                for (int fn = 0; fn < 8; ++fn) {
                    mma16816(acc[fm][fn], a0f[fm], b0f[fn]);
                    mma16816(acc[fm][fn], a0f[fm], b1f[fn]);
                    mma16816(acc[fm][fn], a1f[fm], b0f[fn]);
                }
        }
        __syncthreads();
    }

    // epilogue: bias (+gelu), float2 stores
    #pragma unroll
    for (int fm = 0; fm < 2; ++fm) {
        const int row0 = bm + wm * 32 + fm * 16 + g;
        #pragma unroll
        for (int fn = 0; fn < 8; ++fn) {
            const int col = bn + wn * 64 + fn * 8 + 2 * c;
            const float bv0 = __ldg(&bias[col]);
            const float bv1 = __ldg(&bias[col + 1]);
            float o0 = acc[fm][fn][0] + bv0;
            float o1 = acc[fm][fn][1] + bv1;
            float o2 = acc[fm][fn][2] + bv0;
            float o3 = acc[fm][fn][3] + bv1;
            if (GELU) { o0 = gelu_f(o0); o1 = gelu_f(o1); o2 = gelu_f(o2); o3 = gelu_f(o3); }
            *reinterpret_cast<float2*>(C + (size_t)row0 * N + col)       = make_float2(o0, o1);
            *reinterpret_cast<float2*>(C + (size_t)(row0 + 8) * N + col) = make_float2(o2, o3);
        }
    }
}

// ---------------------------------------------------------------------------
// Attention (fp32, unchanged from passing baseline)
// ---------------------------------------------------------------------------
__global__ __launch_bounds__(256) void attn_scores(
    const float* __restrict__ qkv, float* __restrict__ scr)
{
    const int tt = blockIdx.x;
    const int st = blockIdx.y;
    if (tt > st) return;
    const int hd = blockIdx.z;
    const int b  = hd >> 4, n = hd & 15;

    const float* Q  = qkv + (size_t)b * SEQ * H3 + n * HDIM;
    const float* Kp = Q + HID;

    __shared__ float Qs[32][68];
    __shared__ float Ks[32][68];

    const int tid = threadIdx.x;
    const int tx = tid & 15, ty = tid >> 4;
    const int s0 = st * 64, t0 = tt * 64;

    float acc[4][4] = {};

    for (int k0 = 0; k0 < HDIM; k0 += 32) {
        #pragma unroll
        for (int i = 0; i < 2; i++) {
            int f   = tid + i * 256;
            int row = f >> 3;
            int kc  = (f & 7) * 4;
            float4 q = *(const float4*)(Q  + (size_t)(s0+row) * H3 + k0 + kc);
            Qs[kc+0][row] = q.x; Qs[kc+1][row] = q.y;
            Qs[kc+2][row] = q.z; Qs[kc+3][row] = q.w;
            float4 k = *(const float4*)(Kp + (size_t)(t0+row) * H3 + k0 + kc);
            Ks[kc+0][row] = k.x; Ks[kc+1][row] = k.y;
            Ks[kc+2][row] = k.z; Ks[kc+3][row] = k.w;
        }
        __syncthreads();
        #pragma unroll
        for (int kk = 0; kk < 32; kk++) {
            float4 av = *(const float4*)&Qs[kk][ty*4];
            float4 bv = *(const float4*)&Ks[kk][tx*4];
            float a[4] = {av.x, av.y, av.z, av.w};
            float bb[4] = {bv.x, bv.y, bv.z, bv.w};
            #pragma unroll
            for (int i = 0; i < 4; i++)
                #pragma unroll
                for (int j = 0; j < 4; j++)
                    acc[i][j] += a[i] * bb[j];
        }
        __syncthreads();
    }

    const float scale = 0.08838834764831845f;
    #pragma unroll
    for (int i = 0; i < 4; i++) {
        int s = s0 + ty*4 + i;
        float4* dst = (float4*)(scr + ((size_t)hd * SEQ + s) * SEQ + t0 + tx*4);
        dst[0] = make_float4(acc[i][0]*scale, acc[i][1]*scale,
                             acc[i][2]*scale, acc[i][3]*scale);
    }
}

__global__ __launch_bounds__(256) void softmax_causal(float* __restrict__ scr)
{
    const int s  = blockIdx.x;
    const int hd = blockIdx.y;
    float* row = scr + ((size_t)hd * SEQ + s) * SEQ;
    const int len = s + 1;
    const int tid = threadIdx.x;

    float e[4];
    float mx = -1e30f;
    #pragma unroll
    for (int i = 0; i < 4; i++) {
        int t = tid + i*256;
        e[i] = (t < len) ? row[t] : -1e30f;
        mx = fmaxf(mx, e[i]);
    }
    mx = blockReduceMax256(mx);

    float sum = 0.f;
    #pragma unroll
    for (int i = 0; i < 4; i++) {
        int t = tid + i*256;
        if (t < len) { e[i] = expf(e[i] - mx); sum += e[i]; }
        else e[i] = 0.f;
    }
    sum = blockReduceSum256(sum);
    const float inv = 1.0f / sum;

    const int tile_end = ((s >> 6) + 1) << 6;
    #pragma unroll
    for (int i = 0; i < 4; i++) {
        int t = tid + i*256;
        if (t < len)            row[t] = e[i] * inv;
        else if (t < tile_end)  row[t] = 0.f;
    }
}

__global__ __launch_bounds__(256) void attn_pv(
    const float* __restrict__ scr, const float* __restrict__ qkv,
    float* __restrict__ ctx)
{
    const int st = blockIdx.x;
    const int hd = blockIdx.y;
    const int b  = hd >> 4, n = hd & 15;

    const float* V = qkv + (size_t)b * SEQ * H3 + 2*HID + n * HDIM;
    const float* P = scr + ((size_t)hd * SEQ + st*64) * SEQ;

    __shared__ float Ps[64][36];
    __shared__ float Vs[32][128];

    const int tid = threadIdx.x;
    const int tr = tid >> 5;
    const int tc = tid & 31;

    float acc[8][4] = {};
    const int nk = (st + 1) * 64;

    for (int t0 = 0; t0 < nk; t0 += 32) {
        #pragma unroll
        for (int i = 0; i < 2; i++) {
            int f   = tid + i*256;
            int row = f >> 3;
            int kc  = (f & 7) * 4;
            float4 p = *(const float4*)(P + (size_t)row * SEQ + t0 + kc);
            *(float4*)&Ps[row][kc] = p;
        }
        #pragma unroll
        for (int i = 0; i < 4; i++) {
            int f   = tid + i*256;
            int row = f >> 5;
            int c   = (f & 31) * 4;
            float4 v = *(const float4*)(V + (size_t)(t0+row) * H3 + c);
            *(float4*)&Vs[row][c] = v;
        }
        __syncthreads();

        #pragma unroll
        for (int kk = 0; kk < 32; kk++) {
            float4 vv = *(const float4*)&Vs[kk][tc*4];
            #pragma unroll
            for (int j = 0; j < 8; j++) {
                float p = Ps[tr*8 + j][kk];
                acc[j][0] += p * vv.x;
                acc[j][1] += p * vv.y;
                acc[j][2] += p * vv.z;
                acc[j][3] += p * vv.w;
            }
        }
        __syncthreads();
    }

    #pragma unroll
    for (int j = 0; j < 8; j++) {
        int s = st*64 + tr*8 + j;
        float4* dst = (float4*)(ctx + ((size_t)b*SEQ + s) * HID + n*HDIM + tc*4);
        dst[0] = make_float4(acc[j][0], acc[j][1], acc[j][2], acc[j][3]);
    }
}

// ---------------------------------------------------------------------------
// Host side
// ---------------------------------------------------------------------------
static float* symaddrf(const void* sym) {
    void* p = nullptr;
    cudaGetSymbolAddress(&p, sym);
    return (float*)p;
}
static __nv_bfloat16* symaddrb(const void* sym) {
    void* p = nullptr;
    cudaGetSymbolAddress(&p, sym);
    return (__nv_bfloat16*)p;
}

static void split_launch(const float* s, __nv_bfloat16* hi, __nv_bfloat16* lo, size_t n) {
    int n4 = (int)(n / 4);
    split_fp32_bf16<<<(n4 + 255) / 256, 256>>>(s, hi, lo, n4);
}

static void gemm_launch(const __nv_bfloat16* a0, const __nv_bfloat16* a1,
                        const __nv_bfloat16* b0, const __nv_bfloat16* b1,
                        const float* bias, float* C, int M, int N, int K, bool gelu) {
    dim3 grid(N / 128, M / 128);
    if (gelu) gemm_tc<1><<<grid, 256, GEMM_SMEM_DYN>>>(a0, a1, b0, b1, bias, C, M, N, K);
    else      gemm_tc<0><<<grid, 256, GEMM_SMEM_DYN>>>(a0, a1, b0, b1, bias, C, M, N, K);
}

extern "C" void kernel_launch(void* const* d_in, const int* in_sizes, int n_in,
                              void* d_out, int out_size)
{
    const float* hidden  = (const float*)d_in[0];
    const float* qkv_w   = (const float*)d_in[2];
    const float* qkv_b   = (const float*)d_in[3];
    const float* dense_w = (const float*)d_in[4];
    const float* dense_b = (const float*)d_in[5];
    const float* mlp_w1  = (const float*)d_in[6];
    const float* mlp_b1  = (const float*)d_in[7];
    const float* mlp_w2  = (const float*)d_in[8];
    const float* mlp_b2  = (const float*)d_in[9];
    const float* ln_in_g   = (const float*)d_in[10];
    const float* ln_in_b   = (const float*)d_in[11];
    const float* ln_post_g = (const float*)d_in[12];
    const float* ln_post_b = (const float*)d_in[13];
    const float* ln_s1_g   = (const float*)d_in[14];
    const float* ln_s1_b   = (const float*)d_in[15];
    const float* ln_s2_g   = (const float*)d_in[16];
    const float* ln_s2_b   = (const float*)d_in[17];

    cudaFuncSetAttribute(gemm_tc<0>, cudaFuncAttributeMaxDynamicSharedMemorySize, GEMM_SMEM_DYN);
    cudaFuncSetAttribute(gemm_tc<1>, cudaFuncAttributeMaxDynamicSharedMemorySize, GEMM_SMEM_DYN);

    float* h   = symaddrf(g_h);
    float* x   = symaddrf(g_x);
    float* qkv = symaddrf(g_qkv);
    float* scr = symaddrf(g_scr);
    float* ctx = symaddrf(g_ctx);
    float* att = symaddrf(g_att);
    float* h2  = symaddrf(g_h2);
    float* m1  = symaddrf(g_m1);
    float* m2  = symaddrf(g_m2);
    __nv_bfloat16* a0 = symaddrb(g_a0);
    __nv_bfloat16* a1 = symaddrb(g_a1);
    __nv_bfloat16* w0 = symaddrb(g_w0);
    __nv_bfloat16* w1 = symaddrb(g_w1);
    float* out = (float*)d_out;

    const size_t hbytes = (size_t)ROWS * HID * sizeof(float);
    cudaMemcpyAsync(h, hidden, hbytes, cudaMemcpyDeviceToDevice, 0);

    for (int l = 0; l < LAYERS; l++) {
        const float* l_qkv_w   = qkv_w   + (size_t)l * H3 * HID;
        const float* l_qkv_b   = qkv_b   + (size_t)l * H3;
        const float* l_dense_w = dense_w + (size_t)l * HID * HID;
        const float* l_dense_b = dense_b + (size_t)l * HID;
        const float* l_w1      = mlp_w1  + (size_t)l * H4 * HID;
        const float* l_b1      = mlp_b1  + (size_t)l * H4;
        const float* l_w2      = mlp_w2  + (size_t)l * HID * H4;
        const float* l_b2      = mlp_b2  + (size_t)l * HID;

        // x = LN_in(h)
        ln_kernel<<<ROWS, 256>>>(h, ln_in_g + l*HID, ln_in_b + l*HID, nullptr, x);

        // qkv = x @ qkv_w^T + qkv_b
        split_launch(x, a0, a1, (size_t)ROWS * HID);
        split_launch(l_qkv_w, w0, w1, (size_t)H3 * HID);
        gemm_launch(a0, a1, w0, w1, l_qkv_b, qkv, ROWS, H3, HID, false);

        // attention (fp32)
        attn_scores<<<dim3(16, 16, NHEADS_TOT), 256>>>(qkv, scr);
        softmax_causal<<<dim3(SEQ, NHEADS_TOT), 256>>>(scr);
        attn_pv<<<dim3(16, NHEADS_TOT), 256>>>(scr, qkv, ctx);

        // attn_out = ctx @ dense_w^T + dense_b
        split_launch(ctx, a0, a1, (size_t)ROWS * HID);
        split_launch(l_dense_w, w0, w1, (size_t)HID * HID);
        gemm_launch(a0, a1, w0, w1, l_dense_b, att, ROWS, HID, HID, false);

        // h2 = h + LN_s1(attn_out)
        ln_kernel<<<ROWS, 256>>>(att, ln_s1_g + l*HID, ln_s1_b + l*HID, h, h2);

        // y = LN_post(h2)
        ln_kernel<<<ROWS, 256>>>(h2, ln_post_g + l*HID, ln_post_b + l*HID, nullptr, x);

        // m1 = gelu(y @ w1^T + b1)
        split_launch(x, a0, a1, (size_t)ROWS * HID);
        split_launch(l_w1, w0, w1, (size_t)H4 * HID);
        gemm_launch(a0, a1, w0, w1, l_b1, m1, ROWS, H4, HID, true);

        // m2 = m1 @ w2^T + b2
        split_launch(m1, a0, a1, (size_t)ROWS * H4);
        split_launch(l_w2, w0, w1, (size_t)HID * H4);
        gemm_launch(a0, a1, w0, w1, l_b2, m2, ROWS, HID, H4, false);

        // h = h2 + LN_s2(m2)
        ln_kernel<<<ROWS, 256>>>(m2, ln_s2_g + l*HID, ln_s2_b + l*HID, h2, h);
    }

    cudaMemcpyAsync(out, h, hbytes, cudaMemcpyDeviceToDevice, 0);
}

// round 4
// speedup vs baseline: 4.3945x; 1.1779x over previous
#include <cuda_runtime.h>
#include <cuda_bf16.h>
#include <math.h>
#include <stdint.h>

// Problem constants
#define LAYERS 2
#define BATCH  4
#define SEQ    1024
#define HID    2048
#define NHEAD  16
#define HDIM   128
#define H3     (3*HID)
#define H4     (4*HID)
#define ROWS   (BATCH*SEQ)
#define NHEADS_TOT (BATCH*NHEAD)
#define EPSV   1e-5f

typedef __nv_bfloat16 bf16;

// ---------------------------------------------------------------------------
// Scratch (device globals)
// ---------------------------------------------------------------------------
__device__ float g_h   [(size_t)ROWS*HID];
__device__ float g_att [(size_t)ROWS*HID];
__device__ float g_h2  [(size_t)ROWS*HID];
__device__ float g_m2  [(size_t)ROWS*HID];
__device__ float g_scr [(size_t)NHEADS_TOT*SEQ*SEQ];
// bf16 split buffers
__device__ bf16 g_a0 [(size_t)ROWS*HID];     // LN output splits
__device__ bf16 g_a1 [(size_t)ROWS*HID];
__device__ bf16 g_w0 [(size_t)H4*HID];       // weight splits
__device__ bf16 g_w1 [(size_t)H4*HID];
__device__ bf16 g_qkv0[(size_t)ROWS*H3];
__device__ bf16 g_qkv1[(size_t)ROWS*H3];
__device__ bf16 g_p0 [(size_t)NHEADS_TOT*SEQ*SEQ];
__device__ bf16 g_p1 [(size_t)NHEADS_TOT*SEQ*SEQ];
__device__ bf16 g_c0 [(size_t)ROWS*HID];     // ctx splits
__device__ bf16 g_c1 [(size_t)ROWS*HID];
__device__ bf16 g_m1h[(size_t)ROWS*H4];      // mlp mid splits
__device__ bf16 g_m1l[(size_t)ROWS*H4];

// ---------------------------------------------------------------------------
// Helpers
// ---------------------------------------------------------------------------
__device__ __forceinline__ uint32_t smem_u32(const void* p) {
    uint32_t a;
    asm("{ .reg .u64 t; cvta.to.shared.u64 t, %1; cvt.u32.u64 %0, t; }"
        : "=r"(a) : "l"(p));
    return a;
}
__device__ __forceinline__ void cp16(uint32_t dst, const void* src) {
    asm volatile("cp.async.cg.shared.global [%0], [%1], 16;"
                 :: "r"(dst), "l"(src) : "memory");
}
__device__ __forceinline__ void cp_commit() {
    asm volatile("cp.async.commit_group;" ::: "memory");
}
template<int N> __device__ __forceinline__ void cp_wait() {
    asm volatile("cp.async.wait_group %0;" :: "n"(N) : "memory");
}
__device__ __forceinline__ void mma16816(float* d, const uint32_t* a, const uint32_t* b) {
    asm volatile(
        "mma.sync.aligned.m16n8k16.row.col.f32.bf16.bf16.f32 "
        "{%0,%1,%2,%3}, {%4,%5,%6,%7}, {%8,%9}, {%0,%1,%2,%3};"
        : "+f"(d[0]), "+f"(d[1]), "+f"(d[2]), "+f"(d[3])
        : "r"(a[0]), "r"(a[1]), "r"(a[2]), "r"(a[3]), "r"(b[0]), "r"(b[1]));
}
__device__ __forceinline__ void ldsm4(uint32_t* r, uint32_t addr) {
    asm volatile("ldmatrix.sync.aligned.m8n8.x4.shared.b16 {%0,%1,%2,%3}, [%4];"
                 : "=r"(r[0]), "=r"(r[1]), "=r"(r[2]), "=r"(r[3]) : "r"(addr));
}
__device__ __forceinline__ void ldsm4t(uint32_t* r, uint32_t addr) {
    asm volatile("ldmatrix.sync.aligned.m8n8.x4.trans.shared.b16 {%0,%1,%2,%3}, [%4];"
                 : "=r"(r[0]), "=r"(r[1]), "=r"(r[2]), "=r"(r[3]) : "r"(addr));
}
__device__ __forceinline__ float gelu_f(float x) {
    float inner = 0.7978845608028654f * x * (1.0f + 0.044715f * x * x);
    return 0.5f * x * (1.0f + tanhf(inner));
}
__device__ __forceinline__ void st_split2(bf16* H, bf16* L, size_t off, float x, float y) {
    bf16 hx = __float2bfloat16(x), hy = __float2bfloat16(y);
    bf16 lx = __float2bfloat16(x - __bfloat162float(hx));
    bf16 ly = __float2bfloat16(y - __bfloat162float(hy));
    *reinterpret_cast<__nv_bfloat162*>(H + off) = __halves2bfloat162(hx, hy);
    *reinterpret_cast<__nv_bfloat162*>(L + off) = __halves2bfloat162(lx, ly);
}

// ---------------------------------------------------------------------------
// Block reductions
// ---------------------------------------------------------------------------
__device__ __forceinline__ float blockReduceSum256(float v) {
    __shared__ float sm[8];
    int lane = threadIdx.x & 31, w = threadIdx.x >> 5;
    #pragma unroll
    for (int o = 16; o > 0; o >>= 1) v += __shfl_xor_sync(0xffffffffu, v, o);
    if (lane == 0) sm[w] = v;
    __syncthreads();
    float r = sm[0];
    #pragma unroll
    for (int i = 1; i < 8; i++) r += sm[i];
    __syncthreads();
    return r;
}
__device__ __forceinline__ float blockReduceMax256(float v) {
    __shared__ float sm[8];
    int lane = threadIdx.x & 31, w = threadIdx.x >> 5;
    #pragma unroll
    for (int o = 16; o > 0; o >>= 1) v = fmaxf(v, __shfl_xor_sync(0xffffffffu, v, o));
    if (lane == 0) sm[w] = v;
    __syncthreads();
    float r = sm[0];
    #pragma unroll
    for (int i = 1; i < 8; i++) r = fmaxf(r, sm[i]);
    __syncthreads();
    return r;
}

// ---------------------------------------------------------------------------
// LayerNorm variants
// ---------------------------------------------------------------------------
__global__ __launch_bounds__(256) void ln_kernel(
    const float* __restrict__ x, const float* __restrict__ gamma,
    const float* __restrict__ beta, const float* __restrict__ res,
    float* __restrict__ out)
{
    const int row = blockIdx.x;
    const int tid = threadIdx.x;
    const float* xr = x + (size_t)row * HID;

    float v[8];
    float s = 0.f;
    #pragma unroll
    for (int i = 0; i < 8; i++) { v[i] = xr[i*256 + tid]; s += v[i]; }
    s = blockReduceSum256(s);
    const float mean = s * (1.0f / HID);

    float q = 0.f;
    #pragma unroll
    for (int i = 0; i < 8; i++) { float d = v[i] - mean; q += d * d; }
    q = blockReduceSum256(q);
    const float rstd = rsqrtf(q * (1.0f / HID) + EPSV);

    float* orow = out + (size_t)row * HID;
    const float* rrow = res + (size_t)row * HID;
    #pragma unroll
    for (int i = 0; i < 8; i++) {
        int c = i*256 + tid;
        orow[c] = rrow[c] + (v[i] - mean) * rstd * gamma[c] + beta[c];
    }
}

// LN with split bf16 output (no residual)
__global__ __launch_bounds__(256) void ln_split_kernel(
    const float* __restrict__ x, const float* __restrict__ gamma,
    const float* __restrict__ beta, bf16* __restrict__ hi, bf16* __restrict__ lo)
{
    const int row = blockIdx.x;
    const int tid = threadIdx.x;
    const float* xr = x + (size_t)row * HID;
    const int cb = tid * 8;

    float v[8];
    *reinterpret_cast<float4*>(v)     = *reinterpret_cast<const float4*>(xr + cb);
    *reinterpret_cast<float4*>(v + 4) = *reinterpret_cast<const float4*>(xr + cb + 4);
    float s = 0.f;
    #pragma unroll
    for (int i = 0; i < 8; i++) s += v[i];
    s = blockReduceSum256(s);
    const float mean = s * (1.0f / HID);

    float q = 0.f;
    #pragma unroll
    for (int i = 0; i < 8; i++) { float d = v[i] - mean; q += d * d; }
    q = blockReduceSum256(q);
    const float rstd = rsqrtf(q * (1.0f / HID) + EPSV);

    const size_t ob = (size_t)row * HID + cb;
    #pragma unroll
    for (int i = 0; i < 8; i += 2) {
        float o0 = (v[i]   - mean) * rstd * gamma[cb+i]   + beta[cb+i];
        float o1 = (v[i+1] - mean) * rstd * gamma[cb+i+1] + beta[cb+i+1];
        st_split2(hi, lo, ob + i, o0, o1);
    }
}

// ---------------------------------------------------------------------------
// fp32 -> bf16 hi/lo split (weights)
// ---------------------------------------------------------------------------
__global__ __launch_bounds__(256) void split_fp32_bf16(
    const float* __restrict__ src, bf16* __restrict__ hi,
    bf16* __restrict__ lo, int n4)
{
    int i = blockIdx.x * 256 + threadIdx.x;
    if (i >= n4) return;
    float4 v = reinterpret_cast<const float4*>(src)[i];
    st_split2(hi, lo, (size_t)i * 4,     v.x, v.y);
    st_split2(hi, lo, (size_t)i * 4 + 2, v.z, v.w);
}

// ---------------------------------------------------------------------------
// Common 128x128 split-3 bf16 mma body.
//   C = (A0+A1) @ (B0+B1)^T, dropping A1*B1; A/B staged via cp.async,
//   fragments via ldmatrix. BTRANS=1: B source is [k][n] row-major (V tile).
// smem: 2 stages x 40960B; tile slots of 10240B at A0/A1/B0/B1.
// ---------------------------------------------------------------------------
#define STAGE_BYTES 40960
#define GEMM_SMEM_DYN (2*STAGE_BYTES)

template<int GELU, int HAS_BIAS, int OUT_SPLIT, int BTRANS>
__device__ __forceinline__ void gemm128_body(
    const bf16* __restrict__ A0b, const bf16* __restrict__ A1b, int lda,
    const bf16* __restrict__ B0b, const bf16* __restrict__ B1b, int ldb,
    const float* __restrict__ bias, float scale,
    float* __restrict__ Cf, bf16* __restrict__ Ch, bf16* __restrict__ Cl,
    int ldc, int K)
{
    extern __shared__ uint32_t smw[];
    const uint32_t smbase = smem_u32(smw);

    const int tid = threadIdx.x;
    const int wid = tid >> 5, lane = tid & 31;
    const int wm = wid & 3, wn = wid >> 2;
    const int g = lane >> 2, c = lane & 3;

    const char* pA0 = (const char*)A0b;
    const char* pA1 = (const char*)A1b;
    const char* pB0 = (const char*)B0b;
    const char* pB1 = (const char*)B1b;
    const size_t la = (size_t)lda * 2, lb = (size_t)ldb * 2;

    auto load_stage = [&](int it, int buf) {
        const uint32_t sb = smbase + (uint32_t)buf * STAGE_BYTES;
        if (BTRANS == 0) {
            #pragma unroll
            for (int i = 0; i < 8; i++) {
                int idx = tid + i * 256;          // 0..2047
                int t  = idx >> 9;
                int r  = (idx >> 2) & 127;
                int ch = idx & 3;
                const char* base = (t == 0) ? pA0 : (t == 1) ? pA1 : (t == 2) ? pB0 : pB1;
                size_t stride = (t < 2) ? la : lb;
                cp16(sb + (uint32_t)(t * 10240 + r * 80 + ch * 16),
                     base + (size_t)r * stride + (size_t)it * 64 + ch * 16);
            }
        } else {
            #pragma unroll
            for (int i = 0; i < 4; i++) {         // A (P): 2 splits x 128 rows x 4 chunks
                int idx = tid + i * 256;
                int sp = idx >> 9;
                int r  = (idx >> 2) & 127;
                int ch = idx & 3;
                const char* base = sp ? pA1 : pA0;
                cp16(sb + (uint32_t)(sp * 10240 + r * 80 + ch * 16),
                     base + (size_t)r * la + (size_t)it * 64 + ch * 16);
            }
            #pragma unroll
            for (int i = 0; i < 4; i++) {         // B (V): 2 splits x 32 rows x 16 chunks
                int idx = tid + i * 256;
                int sp = idx >> 9;
                int r  = (idx >> 4) & 31;
                int ch = idx & 15;
                const char* base = sp ? pB1 : pB0;
                cp16(sb + (uint32_t)(20480 + sp * 10240 + r * 256 + ((ch ^ (r & 7)) * 16)),
                     base + (size_t)(it * 32 + r) * lb + ch * 16);
            }
        }
    };

    // ldmatrix per-thread offsets
    const uint32_t a_off = (uint32_t)((wm * 32 + (lane & 15)) * 80 + ((lane & 16) ? 16 : 0));
    const uint32_t b_nt  = (uint32_t)((wn * 64 + (lane & 7) + ((lane & 16) ? 8 : 0)) * 80
                                      + ((lane & 8) ? 16 : 0));
    const int t0l = lane & 15;
    const int cb3 = wn * 8 + ((lane & 16) ? 1 : 0);

    float acc[2][8][4];
    #pragma unroll
    for (int i = 0; i < 2; i++)
        #pragma unroll
        for (int j = 0; j < 8; j++)
            #pragma unroll
            for (int k = 0; k < 4; k++) acc[i][j][k] = 0.f;

    const int nIter = K >> 5;
    load_stage(0, 0);
    cp_commit();

    for (int it = 0; it < nIter; ++it) {
        const int buf = it & 1;
        if (it + 1 < nIter) {
            load_stage(it + 1, buf ^ 1);
            cp_commit();
            cp_wait<1>();
        } else {
            cp_wait<0>();
        }
        __syncthreads();

        const uint32_t sb = smbase + (uint32_t)buf * STAGE_BYTES;
        #pragma unroll
        for (int ks = 0; ks < 2; ++ks) {
            uint32_t a0r[2][4], a1r[2][4];
            #pragma unroll
            for (int fm = 0; fm < 2; ++fm) {
                uint32_t ao = sb + a_off + fm * 1280 + ks * 32;
                ldsm4(a0r[fm], ao);
                ldsm4(a1r[fm], ao + 10240);
            }
            #pragma unroll
            for (int fn2 = 0; fn2 < 4; ++fn2) {
                uint32_t b0r[4], b1r[4];
                if (BTRANS == 0) {
                    uint32_t bo = sb + 20480 + b_nt + fn2 * 1280 + ks * 32;
                    ldsm4(b0r, bo);
                    ldsm4(b1r, bo + 10240);
                } else {
                    int t = ks * 16 + t0l;
                    uint32_t bo = sb + 20480
                        + (uint32_t)(t * 256 + (((cb3 + fn2 * 2) ^ (t & 7)) * 16));
                    ldsm4t(b0r, bo);
                    ldsm4t(b1r, bo + 10240);
                }
                #pragma unroll
                for (int fm = 0; fm < 2; ++fm) {
                    mma16816(acc[fm][2*fn2],   a0r[fm], b0r);
                    mma16816(acc[fm][2*fn2],   a0r[fm], b1r);
                    mma16816(acc[fm][2*fn2],   a1r[fm], b0r);
                    mma16816(acc[fm][2*fn2+1], a0r[fm], b0r + 2);
                    mma16816(acc[fm][2*fn2+1], a0r[fm], b1r + 2);
                    mma16816(acc[fm][2*fn2+1], a1r[fm], b0r + 2);
                }
            }
        }
        __syncthreads();
    }

    // epilogue
    #pragma unroll
    for (int fm = 0; fm < 2; ++fm) {
        const int r0 = wm * 32 + fm * 16 + g;
        #pragma unroll
        for (int fn = 0; fn < 8; ++fn) {
            const int col = wn * 64 + fn * 8 + 2 * c;
            float bv0 = 0.f, bv1 = 0.f;
            if (HAS_BIAS) { bv0 = __ldg(&bias[col]); bv1 = __ldg(&bias[col + 1]); }
            float o0 = acc[fm][fn][0] * scale + bv0;
            float o1 = acc[fm][fn][1] * scale + bv1;
            float o2 = acc[fm][fn][2] * scale + bv0;
            float o3 = acc[fm][fn][3] * scale + bv1;
            if (GELU) { o0 = gelu_f(o0); o1 = gelu_f(o1); o2 = gelu_f(o2); o3 = gelu_f(o3); }
            const size_t off0 = (size_t)r0 * ldc + col;
            const size_t off1 = (size_t)(r0 + 8) * ldc + col;
            if (OUT_SPLIT) {
                st_split2(Ch, Cl, off0, o0, o1);
                st_split2(Ch, Cl, off1, o2, o3);
            } else {
                *reinterpret_cast<float2*>(Cf + off0) = make_float2(o0, o1);
                *reinterpret_cast<float2*>(Cf + off1) = make_float2(o2, o3);
            }
        }
    }
}

// ---------------------------------------------------------------------------
// Kernel wrappers
// ---------------------------------------------------------------------------
template<int GELU, int OUT_SPLIT>
__global__ __launch_bounds__(256, 2) void k_gemm(
    const bf16* __restrict__ A0, const bf16* __restrict__ A1,
    const bf16* __restrict__ B0, const bf16* __restrict__ B1,
    const float* __restrict__ bias,
    float* __restrict__ Cf, bf16* __restrict__ Ch, bf16* __restrict__ Cl,
    int M, int N, int K)
{
    const int bm = blockIdx.y * 128;
    const int bn = blockIdx.x * 128;
    const size_t aoff = (size_t)bm * K;
    const size_t boff = (size_t)bn * K;
    const size_t coff = (size_t)bm * N + bn;
    gemm128_body<GELU, 1, OUT_SPLIT, 0>(
        A0 + aoff, A1 + aoff, K, B0 + boff, B1 + boff, K,
        bias + bn, 1.0f,
        OUT_SPLIT ? nullptr : (Cf + coff),
        OUT_SPLIT ? (Ch + coff) : nullptr,
        OUT_SPLIT ? (Cl + coff) : nullptr,
        N, K);
}

__global__ __launch_bounds__(256, 2) void k_scores(
    const bf16* __restrict__ q0, const bf16* __restrict__ q1,
    float* __restrict__ scr)
{
    const int tt = blockIdx.x, st = blockIdx.y;
    if (tt > st) return;
    const int hd = blockIdx.z, b = hd >> 4, n = hd & 15;
    const size_t qoff = ((size_t)b * SEQ + (size_t)st * 128) * H3 + (size_t)n * HDIM;
    const size_t koff = ((size_t)b * SEQ + (size_t)tt * 128) * H3 + HID + (size_t)n * HDIM;
    float* C = scr + ((size_t)hd * SEQ + (size_t)st * 128) * SEQ + (size_t)tt * 128;
    gemm128_body<0, 0, 0, 0>(
        q0 + qoff, q1 + qoff, H3, q0 + koff, q1 + koff, H3,
        nullptr, 0.08838834764831845f, C, nullptr, nullptr, SEQ, HDIM);
}

__global__ __launch_bounds__(256, 2) void k_pv(
    const bf16* __restrict__ p0, const bf16* __restrict__ p1,
    const bf16* __restrict__ v0, const bf16* __restrict__ v1,
    bf16* __restrict__ ch, bf16* __restrict__ cl)
{
    const int st = blockIdx.x, hd = blockIdx.y, b = hd >> 4, n = hd & 15;
    const size_t poff = ((size_t)hd * SEQ + (size_t)st * 128) * SEQ;
    const size_t voff = (size_t)b * SEQ * H3 + 2 * HID + (size_t)n * HDIM;
    const size_t coff = ((size_t)b * SEQ + (size_t)st * 128) * HID + (size_t)n * HDIM;
    gemm128_body<0, 0, 1, 1>(
        p0 + poff, p1 + poff, SEQ, v0 + voff, v1 + voff, H3,
        nullptr, 1.0f, nullptr, ch + coff, cl + coff, HID, (st + 1) * 128);
}

// ---------------------------------------------------------------------------
// Causal softmax: fp32 scores -> split bf16 probs, zero-filled to 128-tile end
// ---------------------------------------------------------------------------
__global__ __launch_bounds__(256) void softmax_split(
    const float* __restrict__ scr, bf16* __restrict__ p0, bf16* __restrict__ p1)
{
    const int s  = blockIdx.x;
    const int hd = blockIdx.y;
    const size_t rb = ((size_t)hd * SEQ + s) * SEQ;
    const float* row = scr + rb;
    const int len = s + 1;
    const int base = threadIdx.x * 4;

    float4 v = *reinterpret_cast<const float4*>(row + base);
    float e[4] = {v.x, v.y, v.z, v.w};
    float mx = -1e30f;
    #pragma unroll
    for (int j = 0; j < 4; j++) {
        if (base + j >= len) e[j] = -1e30f;
        mx = fmaxf(mx, e[j]);
    }
    mx = blockReduceMax256(mx);

    float sum = 0.f;
    #pragma unroll
    for (int j = 0; j < 4; j++) {
        e[j] = (base + j < len) ? expf(e[j] - mx) : 0.f;
        sum += e[j];
    }
    sum = blockReduceSum256(sum);
    const float inv = 1.0f / sum;

    const int tile_end = ((s >> 7) + 1) << 7;
    if (base < tile_end) {
        float o0 = e[0] * inv, o1 = e[1] * inv, o2 = e[2] * inv, o3 = e[3] * inv;
        st_split2(p0, p1, rb + base,     o0, o1);
        st_split2(p0, p1, rb + base + 2, o2, o3);
    }
}

// ---------------------------------------------------------------------------
// Host side
// ---------------------------------------------------------------------------
static float* symaddrf(const void* sym) {
    void* p = nullptr; cudaGetSymbolAddress(&p, sym); return (float*)p;
}
static bf16* symaddrb(const void* sym) {
    void* p = nullptr; cudaGetSymbolAddress(&p, sym); return (bf16*)p;
}
static void split_launch(const float* s, bf16* hi, bf16* lo, size_t n) {
    int n4 = (int)(n / 4);
    split_fp32_bf16<<<(n4 + 255) / 256, 256>>>(s, hi, lo, n4);
}

extern "C" void kernel_launch(void* const* d_in, const int* in_sizes, int n_in,
                              void* d_out, int out_size)
{
    const float* hidden  = (const float*)d_in[0];
    const float* qkv_w   = (const float*)d_in[2];
    const float* qkv_b   = (const float*)d_in[3];
    const float* dense_w = (const float*)d_in[4];
    const float* dense_b = (const float*)d_in[5];
    const float* mlp_w1  = (const float*)d_in[6];
    const float* mlp_b1  = (const float*)d_in[7];
    const float* mlp_w2  = (const float*)d_in[8];
    const float* mlp_b2  = (const float*)d_in[9];
    const float* ln_in_g   = (const float*)d_in[10];
    const float* ln_in_b   = (const float*)d_in[11];
    const float* ln_post_g = (const float*)d_in[12];
    const float* ln_post_b = (const float*)d_in[13];
    const float* ln_s1_g   = (const float*)d_in[14];
    const float* ln_s1_b   = (const float*)d_in[15];
    const float* ln_s2_g   = (const float*)d_in[16];
    const float* ln_s2_b   = (const float*)d_in[17];

    cudaFuncSetAttribute(k_gemm<0,0>, cudaFuncAttributeMaxDynamicSharedMemorySize, GEMM_SMEM_DYN);
    cudaFuncSetAttribute(k_gemm<0,1>, cudaFuncAttributeMaxDynamicSharedMemorySize, GEMM_SMEM_DYN);
    cudaFuncSetAttribute(k_gemm<1,1>, cudaFuncAttributeMaxDynamicSharedMemorySize, GEMM_SMEM_DYN);
    cudaFuncSetAttribute(k_scores,    cudaFuncAttributeMaxDynamicSharedMemorySize, GEMM_SMEM_DYN);
    cudaFuncSetAttribute(k_pv,        cudaFuncAttributeMaxDynamicSharedMemorySize, GEMM_SMEM_DYN);

    float* h   = symaddrf(g_h);
    float* att = symaddrf(g_att);
    float* h2  = symaddrf(g_h2);
    float* m2  = symaddrf(g_m2);
    float* scr = symaddrf(g_scr);
    bf16* a0 = symaddrb(g_a0);   bf16* a1 = symaddrb(g_a1);
    bf16* w0 = symaddrb(g_w0);   bf16* w1 = symaddrb(g_w1);
    bf16* q0 = symaddrb(g_qkv0); bf16* q1 = symaddrb(g_qkv1);
    bf16* p0 = symaddrb(g_p0);   bf16* p1 = symaddrb(g_p1);
    bf16* c0 = symaddrb(g_c0);   bf16* c1 = symaddrb(g_c1);
    bf16* m1h = symaddrb(g_m1h); bf16* m1l = symaddrb(g_m1l);
    float* out = (float*)d_out;

    for (int l = 0; l < LAYERS; l++) {
        const float* hin = (l == 0) ? hidden : h;
        const float* l_qkv_w   = qkv_w   + (size_t)l * H3 * HID;
        const float* l_qkv_b   = qkv_b   + (size_t)l * H3;
        const float* l_dense_w = dense_w + (size_t)l * HID * HID;
        const float* l_dense_b = dense_b + (size_t)l * HID;
        const float* l_w1      = mlp_w1  + (size_t)l * H4 * HID;
        const float* l_b1      = mlp_b1  + (size_t)l * H4;
        const float* l_w2      = mlp_w2  + (size_t)l * HID * H4;
        const float* l_b2      = mlp_b2  + (size_t)l * HID;

        // x = LN_in(h) -> split
        ln_split_kernel<<<ROWS, 256>>>(hin, ln_in_g + l*HID, ln_in_b + l*HID, a0, a1);

        // qkv = x @ qkv_w^T + b  -> split bf16
        split_launch(l_qkv_w, w0, w1, (size_t)H3 * HID);
        k_gemm<0,1><<<dim3(H3/128, ROWS/128), 256, GEMM_SMEM_DYN>>>(
            a0, a1, w0, w1, l_qkv_b, nullptr, q0, q1, ROWS, H3, HID);

        // attention on tensor cores
        k_scores<<<dim3(8, 8, NHEADS_TOT), 256, GEMM_SMEM_DYN>>>(q0, q1, scr);
        softmax_split<<<dim3(SEQ, NHEADS_TOT), 256>>>(scr, p0, p1);
        k_pv<<<dim3(8, NHEADS_TOT), 256, GEMM_SMEM_DYN>>>(p0, p1, q0, q1, c0, c1);

        // attn_out = ctx @ dense_w^T + b  (fp32)
        split_launch(l_dense_w, w0, w1, (size_t)HID * HID);
        k_gemm<0,0><<<dim3(HID/128, ROWS/128), 256, GEMM_SMEM_DYN>>>(
            c0, c1, w0, w1, l_dense_b, att, nullptr, nullptr, ROWS, HID, HID);

        // h2 = h + LN_s1(attn_out)
        ln_kernel<<<ROWS, 256>>>(att, ln_s1_g + l*HID, ln_s1_b + l*HID, hin, h2);

        // y = LN_post(h2) -> split
        ln_split_kernel<<<ROWS, 256>>>(h2, ln_post_g + l*HID, ln_post_b + l*HID, a0, a1);

        // m1 = gelu(y @ w1^T + b1) -> split
        split_launch(l_w1, w0, w1, (size_t)H4 * HID);
        k_gemm<1,1><<<dim3(H4/128, ROWS/128), 256, GEMM_SMEM_DYN>>>(
            a0, a1, w0, w1, l_b1, nullptr, m1h, m1l, ROWS, H4, HID);

        // m2 = m1 @ w2^T + b2 (fp32)
        split_launch(l_w2, w0, w1, (size_t)HID * H4);
        k_gemm<0,0><<<dim3(HID/128, ROWS/128), 256, GEMM_SMEM_DYN>>>(
            m1h, m1l, w0, w1, l_b2, m2, nullptr, nullptr, ROWS, HID, H4);

        // h = h2 + LN_s2(m2)
        ln_kernel<<<ROWS, 256>>>(m2, ln_s2_g + l*HID, ln_s2_b + l*HID, h2, h);
    }

    cudaMemcpyAsync(out, h, (size_t)ROWS * HID * sizeof(float),
                    cudaMemcpyDeviceToDevice, 0);
}